// round 13
// baseline (speedup 1.0000x reference)
#include <cuda_runtime.h>
#include <cuda_bf16.h>
#include <math_constants.h>
#include <cstdint>

#define DIM     64
#define KCODE   1024
#define MAXN    262144
#define EPS_INT 140          // 140 * 2^-21 ~ 6.7e-5 ambiguity window
#define NPART   8192

// ---------------------------------------------------------------------------
// Device scratch (no cudaMalloc allowed)
__device__ int       g_idx[MAXN];
__device__ float     g_wsum2[KCODE];    // exact sequential-chain ||w||^2
__device__ float     g_wsC21[KCODE];    // fl(fl(||w||^2 + 0.25) * 2^21)
__device__ int       g_flagn;
__device__ int       g_flags[MAXN];
__device__ double    g_part[NPART];
// per code: 128 bf16 = [w_hi 64 | w_lo 64]  (256 B)
__device__ __nv_bfloat16 g_wb[KCODE * 128];

// ---------------------------------------------------------------------------
__device__ __forceinline__ uint32_t smem_u32(const void* p) {
    uint32_t a;
    asm("{ .reg .u64 t; cvta.to.shared.u64 t, %1; cvt.u32.u64 %0, t; }"
        : "=r"(a) : "l"(p));
    return a;
}
__device__ __forceinline__ void ldsm_x4(uint32_t& r0, uint32_t& r1,
                                        uint32_t& r2, uint32_t& r3, uint32_t addr) {
    asm volatile("ldmatrix.sync.aligned.m8n8.x4.shared.b16 {%0,%1,%2,%3}, [%4];"
                 : "=r"(r0), "=r"(r1), "=r"(r2), "=r"(r3) : "r"(addr));
}
__device__ __forceinline__ void mma_bf16(float* c, const uint32_t* a,
                                         uint32_t b0, uint32_t b1) {
    asm volatile(
        "mma.sync.aligned.m16n8k16.row.col.f32.bf16.bf16.f32 "
        "{%0,%1,%2,%3}, {%4,%5,%6,%7}, {%8,%9}, {%0,%1,%2,%3};"
        : "+f"(c[0]), "+f"(c[1]), "+f"(c[2]), "+f"(c[3])
        : "r"(a[0]), "r"(a[1]), "r"(a[2]), "r"(a[3]), "r"(b0), "r"(b1));
}

__device__ __forceinline__ void top2(int& m1, int& m2, int s) {
    int lo = min(m1, s);
    int hi = max(m1, s);
    m1 = lo;
    m2 = min(m2, hi);
}

// ---------------------------------------------------------------------------
// Codebook prep: one block per 128 codes, coalesced smem staging.
// Exact sequential ||w||^2 chain (reference semantics) + bf16 hi/lo split.
// Also resets g_flagn (block 0) -- replaces the old k_zero node.
__global__ __launch_bounds__(256, 1)
void k_prep_w(const float* __restrict__ w)
{
    __shared__ __align__(16) float sw[128 * DIM];   // 32KB
    const int tid = threadIdx.x;
    const int k0  = blockIdx.x * 128;

    if (blockIdx.x == 0 && tid == 0) g_flagn = 0;

    // Coalesced stage: 2048 float4
    {
        const float4* src = (const float4*)(w + (size_t)k0 * DIM);
        float4* dst = (float4*)sw;
        #pragma unroll
        for (int i = 0; i < 8; ++i) dst[tid + i * 256] = src[tid + i * 256];
    }
    __syncthreads();

    // Exact sequential-chain sums (threads 0..127, one code each)
    if (tid < 128) {
        const float* r = sw + tid * DIM;
        float s = 0.0f;
        #pragma unroll
        for (int d = 0; d < DIM; ++d)
            s = __fadd_rn(s, __fmul_rn(r[d], r[d]));
        g_wsum2[k0 + tid] = s;
        g_wsC21[k0 + tid] = __fmul_rn(__fadd_rn(s, 0.25f), 2097152.0f);
    }

    // bf16 split, coalesced 2B writes
    for (int i = tid; i < 128 * DIM; i += 256) {
        int row = i >> 6, d = i & 63;
        float v = sw[i];
        __nv_bfloat16 hi = __float2bfloat16(v);
        __nv_bfloat16 lo = __float2bfloat16(__fsub_rn(v, __bfloat162float(hi)));
        g_wb[(size_t)(k0 + row) * 128 + d]      = hi;
        g_wb[(size_t)(k0 + row) * 128 + 64 + d] = lo;
    }
}

// ---------------------------------------------------------------------------
// HMMA argmin filter. NO cp.async: register-staged plain-load double buffer.
// 128 tokens/CTA, 8 warps x M16, static 48KB smem, no reg cap.
// K=192 logical (split bf16): ks0-3 z_hi.w_hi, ks4-7 z_lo.w_hi, ks8-11 z_hi.w_lo
// A: 128 x 256B = 32KB. B: 32-code tiles (8KB) double-buffered.
__global__ __launch_bounds__(256, 1)
void k_argmin_mma(const float* __restrict__ z, float* __restrict__ out_idx)
{
    __shared__ __align__(16) char smem[49152];   // A 32KB | B0 8KB | B1 8KB
    const uint32_t sbA  = smem_u32(smem);
    const uint32_t sbB0 = sbA + 32768;
    const uint32_t sbB1 = sbA + 40960;

    const int tid  = threadIdx.x;
    const int lane = tid & 31;
    const int warp = tid >> 5;
    const int t0   = blockIdx.x * 128;

    // Swizzled destination offsets for this thread's two B chunks
    const int brow0 = tid >> 4,           bc0 = tid & 15;
    const int brow1 = (tid + 256) >> 4,   bc1c = (tid + 256) & 15;
    const uint32_t bo0 = (uint32_t)(brow0 * 256 + ((bc0 ^ (brow0 & 7)) << 4));
    const uint32_t bo1 = (uint32_t)(brow1 * 256 + ((bc1c ^ (brow1 & 7)) << 4));

    // Preload B tile 0 into registers, then store; preload tile 1 regs.
    float4 nx0, nx1;
    {
        const float4* src = (const float4*)g_wb;
        nx0 = src[tid];
        nx1 = src[tid + 256];
        *(float4*)(smem + 32768 + bo0) = nx0;
        *(float4*)(smem + 32768 + bo1) = nx1;
        const float4* src1 = (const float4*)((const char*)g_wb + 8192);
        nx0 = src1[tid];
        nx1 = src1[tid + 256];
    }

    // Stage A: 128 tokens x 256B = [z_hi 64bf16 | z_lo 64bf16], XOR-swizzled.
    {
        const float4* zsrc = (const float4*)(z + (size_t)t0 * DIM);
        #pragma unroll
        for (int it = 0; it < 8; ++it) {
            int ic = tid + it * 256;                // 2048 chunks
            int row = ic >> 4, c = ic & 15;
            int d4 = (c & 7) * 2;
            float4 v0 = zsrc[row * 16 + d4];
            float4 v1 = zsrc[row * 16 + d4 + 1];
            __nv_bfloat162 p0, p1, p2, p3;
            p0.x = __float2bfloat16(v0.x); p0.y = __float2bfloat16(v0.y);
            p1.x = __float2bfloat16(v0.z); p1.y = __float2bfloat16(v0.w);
            p2.x = __float2bfloat16(v1.x); p2.y = __float2bfloat16(v1.y);
            p3.x = __float2bfloat16(v1.z); p3.y = __float2bfloat16(v1.w);
            if (c >= 8) {
                p0.x = __float2bfloat16(__fsub_rn(v0.x, __bfloat162float(p0.x)));
                p0.y = __float2bfloat16(__fsub_rn(v0.y, __bfloat162float(p0.y)));
                p1.x = __float2bfloat16(__fsub_rn(v0.z, __bfloat162float(p1.x)));
                p1.y = __float2bfloat16(__fsub_rn(v0.w, __bfloat162float(p1.y)));
                p2.x = __float2bfloat16(__fsub_rn(v1.x, __bfloat162float(p2.x)));
                p2.y = __float2bfloat16(__fsub_rn(v1.y, __bfloat162float(p2.y)));
                p3.x = __float2bfloat16(__fsub_rn(v1.z, __bfloat162float(p3.x)));
                p3.y = __float2bfloat16(__fsub_rn(v1.w, __bfloat162float(p3.y)));
            }
            uint4 o;
            o.x = *(uint32_t*)&p0; o.y = *(uint32_t*)&p1;
            o.z = *(uint32_t*)&p2; o.w = *(uint32_t*)&p3;
            *(uint4*)(smem + row * 256 + ((c ^ (row & 7)) << 4)) = o;
        }
    }
    __syncthreads();

    // A fragments: warp covers tokens [warp*16, warp*16+16)
    uint32_t a[8][4];
    {
        const int r16   = lane & 15;
        const int chalf = lane >> 4;
        #pragma unroll
        for (int ks = 0; ks < 8; ++ks) {
            int row = warp * 16 + r16;
            int c   = ks * 2 + chalf;
            ldsm_x4(a[ks][0], a[ks][1], a[ks][2], a[ks][3],
                    sbA + row * 256 + ((c ^ (row & 7)) << 4));
        }
    }

    int m1s[2], m2s[2];
    m1s[0] = m1s[1] = 0x7FFFFFFF;
    m2s[0] = m2s[1] = 0x7FFFFFFF;

    const int brow  = (lane & 7) + ((lane >> 4) << 3);
    const int bc1   = (lane >> 3) & 1;
    const int br7   = brow & 7;
    const int klane = 2 * (lane & 3);

    #pragma unroll 1
    for (int t = 0; t < 32; ++t) {
        // buf[t&1] holds tile t; regs hold tile t+1
        const uint32_t bbase = ((t & 1) ? sbB1 : sbB0) + brow * 256;

        #pragma unroll
        for (int ng = 0; ng < 2; ++ng) {
            float acc[2][4];
            #pragma unroll
            for (int nf = 0; nf < 2; ++nf)
                #pragma unroll
                for (int j = 0; j < 4; ++j) acc[nf][j] = 0.0f;

            const uint32_t bgb = bbase + ng * 16 * 256;
            #pragma unroll
            for (int ks = 0; ks < 12; ++ks) {
                const int j = (ks < 8) ? (ks & 3) : ((ks & 3) + 4);
                uint32_t b0, b1, b2, b3;
                ldsm_x4(b0, b1, b2, b3, bgb + (((j * 2 + bc1) ^ br7) << 4));
                const int ka = ks & 7;       // ks 8-11 reuse z_hi frags 0-3
                mma_bf16(acc[0], a[ka], b0, b1);
                mma_bf16(acc[1], a[ka], b2, b3);
            }

            // epilogue: s = rn((b+0.25)*2^21 - 2^22*dot), pack (s<<10)|idx
            const int kb = t * 32 + ng * 16 + klane;
            #pragma unroll
            for (int nf = 0; nf < 2; ++nf) {
                const int kc = kb + nf * 8;
                const float bx = __ldg(&g_wsC21[kc]);
                const float by = __ldg(&g_wsC21[kc + 1]);
                int s0 = (__float2int_rn(__fmaf_rn(-4194304.0f, acc[nf][0], bx)) << 10) | kc;
                int s1 = (__float2int_rn(__fmaf_rn(-4194304.0f, acc[nf][1], by)) << 10) | (kc + 1);
                int s2 = (__float2int_rn(__fmaf_rn(-4194304.0f, acc[nf][2], bx)) << 10) | kc;
                int s3 = (__float2int_rn(__fmaf_rn(-4194304.0f, acc[nf][3], by)) << 10) | (kc + 1);
                top2(m1s[0], m2s[0], s0);
                top2(m1s[0], m2s[0], s1);
                top2(m1s[1], m2s[1], s2);
                top2(m1s[1], m2s[1], s3);
            }
        }

        __syncthreads();   // all warps done with buf[(t+1)&1]'s old contents
        if (t + 1 < 32) {
            uint32_t dstb = ((t + 1) & 1) ? sbB1 : sbB0;
            *(float4*)((char*)smem + (dstb - sbA) + bo0) = nx0;
            *(float4*)((char*)smem + (dstb - sbA) + bo1) = nx1;
            if (t + 2 < 32) {
                const float4* src = (const float4*)((const char*)g_wb
                                                    + (size_t)(t + 2) * 8192);
                nx0 = src[tid];
                nx1 = src[tid + 256];
            }
        }
        __syncthreads();   // stores visible before next compute
    }

    // merge across the 4 lanes sharing each row
    #pragma unroll
    for (int s = 0; s < 2; ++s) {
        #pragma unroll
        for (int d = 1; d <= 2; d <<= 1) {
            int om1 = __shfl_xor_sync(0xffffffffu, m1s[s], d);
            int om2 = __shfl_xor_sync(0xffffffffu, m2s[s], d);
            int hi = max(m1s[s], om1);
            m1s[s] = min(m1s[s], om1);
            m2s[s] = min(min(m2s[s], om2), hi);
        }
    }
    if ((lane & 3) == 0) {
        const int q = lane >> 2;
        #pragma unroll
        for (int s = 0; s < 2; ++s) {
            const int token = t0 + warp * 16 + s * 8 + q;
            const int k1 = m1s[s] & 1023;
            g_idx[token]   = k1;
            out_idx[token] = (float)k1;
            if ((m2s[s] >> 10) - (m1s[s] >> 10) <= EPS_INT) {
                int p = atomicAdd(&g_flagn, 1);
                g_flags[p] = token;
            }
        }
    }
}

// ---------------------------------------------------------------------------
// Exact fallback: bit-exact reference semantics for flagged tokens.
__global__ __launch_bounds__(256)
void k_exact(const float* __restrict__ z,
             const float* __restrict__ w,
             float* __restrict__ out_idx)
{
    const int lane = threadIdx.x & 31;
    const int gw   = (blockIdx.x * blockDim.x + threadIdx.x) >> 5;
    const int nw   = (gridDim.x * blockDim.x) >> 5;
    const int nflag = g_flagn;

    for (int i = gw; i < nflag; i += nw) {
        const size_t token = (size_t)g_flags[i];

        float zr[DIM];
        float a = 0.0f;
        #pragma unroll
        for (int d = 0; d < DIM; ++d) {
            zr[d] = z[token * DIM + d];
            a = __fadd_rn(a, __fmul_rn(zr[d], zr[d]));
        }

        float best = CUDART_INF_F;
        int   bidx = 0;

        for (int k0 = lane; k0 < KCODE; k0 += 128) {
            const float* w0 = w + (size_t)(k0 +  0) * DIM;
            const float* w1 = w + (size_t)(k0 + 32) * DIM;
            const float* w2 = w + (size_t)(k0 + 64) * DIM;
            const float* w3 = w + (size_t)(k0 + 96) * DIM;
            float d0 = 0.0f, d1 = 0.0f, d2 = 0.0f, d3 = 0.0f;
            #pragma unroll
            for (int d = 0; d < DIM; ++d) {
                const float zv = zr[d];
                d0 = __fmaf_rn(zv, w0[d], d0);
                d1 = __fmaf_rn(zv, w1[d], d1);
                d2 = __fmaf_rn(zv, w2[d], d2);
                d3 = __fmaf_rn(zv, w3[d], d3);
            }
            float tt, dd;
            tt = __fadd_rn(a, g_wsum2[k0]);
            dd = __fadd_rn(tt, -__fmul_rn(2.0f, d0));
            if (dd < best) { best = dd; bidx = k0; }
            tt = __fadd_rn(a, g_wsum2[k0 + 32]);
            dd = __fadd_rn(tt, -__fmul_rn(2.0f, d1));
            if (dd < best) { best = dd; bidx = k0 + 32; }
            tt = __fadd_rn(a, g_wsum2[k0 + 64]);
            dd = __fadd_rn(tt, -__fmul_rn(2.0f, d2));
            if (dd < best) { best = dd; bidx = k0 + 64; }
            tt = __fadd_rn(a, g_wsum2[k0 + 96]);
            dd = __fadd_rn(tt, -__fmul_rn(2.0f, d3));
            if (dd < best) { best = dd; bidx = k0 + 96; }
        }

        #pragma unroll
        for (int off = 16; off > 0; off >>= 1) {
            float ov = __shfl_down_sync(0xffffffffu, best, off);
            int   oi = __shfl_down_sync(0xffffffffu, bidx, off);
            if (ov < best || (ov == best && oi < bidx)) { best = ov; bidx = oi; }
        }
        if (lane == 0) {
            g_idx[token]   = bidx;
            out_idx[token] = (float)bidx;
        }
    }
}

// ---------------------------------------------------------------------------
// Gather z_q_st = fl(z + fl(w[idx] - z)); per-block double partial (no atomic).
__global__ __launch_bounds__(512)
void k_gather(const float* __restrict__ z,
              const float* __restrict__ w,
              float* __restrict__ out_zq)
{
    __shared__ double sred[16];
    const int tid = threadIdx.x;
    const size_t token = (size_t)blockIdx.x * 32 + (tid >> 4);
    const int c = tid & 15;

    const int idx = g_idx[token];
    const float4 wv = ((const float4*)(w + (size_t)idx * DIM))[c];
    const float4 zv = ((const float4*)(z + token * DIM))[c];

    const float dx = __fsub_rn(wv.x, zv.x);
    const float dy = __fsub_rn(wv.y, zv.y);
    const float dz = __fsub_rn(wv.z, zv.z);
    const float dw = __fsub_rn(wv.w, zv.w);

    float4 o;
    o.x = __fadd_rn(zv.x, dx);
    o.y = __fadd_rn(zv.y, dy);
    o.z = __fadd_rn(zv.z, dz);
    o.w = __fadd_rn(zv.w, dw);
    ((float4*)out_zq)[token * (DIM / 4) + c] = o;

    double s = (double)__fmul_rn(dx, dx);
    s += (double)__fmul_rn(dy, dy);
    s += (double)__fmul_rn(dz, dz);
    s += (double)__fmul_rn(dw, dw);

    #pragma unroll
    for (int off = 16; off > 0; off >>= 1)
        s += __shfl_down_sync(0xffffffffu, s, off);

    const int wrp = tid >> 5;
    if ((tid & 31) == 0) sred[wrp] = s;
    __syncthreads();

    if (wrp == 0) {
        double v = (tid < 16) ? sred[tid] : 0.0;
        #pragma unroll
        for (int off = 8; off > 0; off >>= 1)
            v += __shfl_down_sync(0xffffffffu, v, off);
        if (tid == 0) g_part[blockIdx.x] = v;
    }
}

// ---------------------------------------------------------------------------
__global__ __launch_bounds__(256)
void k_final(float* __restrict__ out_loss, int total_elems)
{
    __shared__ double sm[8];
    const int tid = threadIdx.x;
    double s = 0.0;
    for (int i = tid; i < NPART; i += 256) s += g_part[i];
    #pragma unroll
    for (int off = 16; off > 0; off >>= 1)
        s += __shfl_down_sync(0xffffffffu, s, off);
    if ((tid & 31) == 0) sm[tid >> 5] = s;
    __syncthreads();
    if (tid == 0) {
        double tot = 0.0;
        #pragma unroll
        for (int i = 0; i < 8; ++i) tot += sm[i];
        const float m = (float)(tot / (double)total_elems);
        out_loss[0] = __fadd_rn(m, __fmul_rn(0.25f, m));
    }
}

// ---------------------------------------------------------------------------
extern "C" void kernel_launch(void* const* d_in, const int* in_sizes, int n_in,
                              void* d_out, int out_size)
{
    const float* z = (const float*)d_in[0];   // (N, 64) fp32
    const float* w = (const float*)d_in[1];   // (1024, 64) fp32

    const int ND = in_sizes[0];
    const int N  = ND / DIM;                  // 262144

    float* out      = (float*)d_out;
    float* out_zq   = out;                    // N*64 floats
    float* out_loss = out + (size_t)N * DIM;  // 1 float
    float* out_idx  = out_loss + 1;           // N floats

    // 5 nodes, no cp.async anywhere, all static smem <= 48KB, no reg caps.
    k_prep_w<<<KCODE / 128, 256>>>(w);
    k_argmin_mma<<<N / 128, 256>>>(z, out_idx);
    k_exact<<<256, 256>>>(z, w, out_idx);
    k_gather<<<N / 32, 512>>>(z, w, out_zq);
    k_final<<<1, 256>>>(out_loss, ND);
}

// round 15
// speedup vs baseline: 1.3221x; 1.3221x over previous
#include <cuda_runtime.h>
#include <cuda_bf16.h>
#include <math_constants.h>
#include <cstdint>

#define DIM     64
#define KCODE   1024
#define MAXN    262144
#define NPART   8192

#define QWF     130048.0f            // w int8 scale: 1024*127
#define TWO21   2097152.0f
#define CZCONST (2.0f * 2097152.0f / 130048.0f)   // 2*2^21/QW

// ---------------------------------------------------------------------------
// Device scratch (no cudaMalloc allowed)
__device__ int       g_idx[MAXN];
__device__ float     g_wsum2[KCODE];    // exact sequential-chain ||w||^2
__device__ float     g_wsC21[KCODE];    // fl(fl(||w||^2 + 0.25) * 2^21)
__device__ int       g_flagn;
__device__ int       g_flags[MAXN];
__device__ double    g_part[NPART];
__device__ int       g_w1max;           // max_k ||w_k||_1 as float-bits (atomicMax)
__device__ uint32_t  g_wq[KCODE * 16];  // per code: 64 int8 packed in 16 u32

// ---------------------------------------------------------------------------
__device__ __forceinline__ int dp4(int a, int b, int c) {
    int r;
    asm("dp4a.s32.s32 %0, %1, %2, %3;" : "=r"(r) : "r"(a), "r"(b), "r"(c));
    return r;
}
__device__ __forceinline__ void top4(int& m1, int& m2, int& m3, int& m4, int s) {
    int t1 = max(m1, s); m1 = min(m1, s);
    int t2 = max(m2, t1); m2 = min(m2, t1);
    int t3 = max(m3, t2); m3 = min(m3, t2);
    m4 = min(m4, t3);
}

// ---------------------------------------------------------------------------
// Codebook prep: exact ||w||^2 chain, score bias, int8 quantization, L1 norm.
__global__ __launch_bounds__(256, 1)
void k_prep_w(const float* __restrict__ w)
{
    __shared__ __align__(16) float sw[128 * DIM];   // 32KB
    const int tid = threadIdx.x;
    const int k0  = blockIdx.x * 128;

    if (blockIdx.x == 0 && tid == 0) g_flagn = 0;

    {   // coalesced stage: 2048 float4
        const float4* src = (const float4*)(w + (size_t)k0 * DIM);
        float4* dst = (float4*)sw;
        #pragma unroll
        for (int i = 0; i < 8; ++i) dst[tid + i * 256] = src[tid + i * 256];
    }
    __syncthreads();

    if (tid < 128) {
        const float* r = sw + tid * DIM;
        const int k = k0 + tid;
        // exact sequential-chain ||w||^2 (reference semantics)
        float s = 0.0f;
        #pragma unroll
        for (int d = 0; d < DIM; ++d)
            s = __fadd_rn(s, __fmul_rn(r[d], r[d]));
        g_wsum2[k] = s;
        g_wsC21[k] = __fmul_rn(__fadd_rn(s, 0.25f), TWO21);

        // L1 norm (inflated for bound soundness) -> global max
        float w1 = 0.0f;
        #pragma unroll
        for (int d = 0; d < DIM; ++d) w1 += fabsf(r[d]);
        atomicMax(&g_w1max, __float_as_int(w1 * 1.000002f));

        // int8 quantization, 4 values per u32 (byte0 = lowest d)
        #pragma unroll
        for (int j = 0; j < 16; ++j) {
            int q0 = __float2int_rn(r[4 * j + 0] * QWF);
            int q1 = __float2int_rn(r[4 * j + 1] * QWF);
            int q2 = __float2int_rn(r[4 * j + 2] * QWF);
            int q3 = __float2int_rn(r[4 * j + 3] * QWF);
            g_wq[(size_t)k * 16 + j] =
                (uint32_t)(q0 & 255) | ((uint32_t)(q1 & 255) << 8) |
                ((uint32_t)(q2 & 255) << 16) | ((uint32_t)(q3 & 255) << 24);
        }
    }
}

// ---------------------------------------------------------------------------
// dp4a argmin filter with sound candidate certificates.
// One token per thread. 16 dp4a per code; top-4 tracked in packed ints.
// Candidates within the provable error window are exact-rescored with the
// bit-exact reference chain; if the 4th-best is inside the window, the token
// goes to the full-scan exact fallback.
__global__ __launch_bounds__(256)
void k_filter(const float* __restrict__ z,
              const float* __restrict__ w,
              float* __restrict__ out_idx)
{
    const int tok = blockIdx.x * 256 + threadIdx.x;
    const float4* zp = (const float4*)(z + (size_t)tok * DIM);

    // Pass 1: zmax + exact sequential ||z||^2 chain (reference order)
    float a = 0.0f, zm = 0.0f;
    #pragma unroll
    for (int i = 0; i < 16; ++i) {
        float4 t = zp[i];
        a = __fadd_rn(a, __fmul_rn(t.x, t.x));
        a = __fadd_rn(a, __fmul_rn(t.y, t.y));
        a = __fadd_rn(a, __fmul_rn(t.z, t.z));
        a = __fadd_rn(a, __fmul_rn(t.w, t.w));
        zm = fmaxf(zm, fmaxf(fmaxf(fabsf(t.x), fabsf(t.y)),
                             fmaxf(fabsf(t.z), fabsf(t.w))));
    }
    const float inv = (zm > 0.0f) ? (127.0f / zm) : 0.0f;
    const float sz  = zm * (1.0f / 127.0f);

    // Pass 2: quantize z (L1-hot reload)
    int zq[16];
    int sabs = 0;
    #pragma unroll
    for (int i = 0; i < 16; ++i) {
        float4 t = zp[i];
        int q0 = __float2int_rn(t.x * inv);
        int q1 = __float2int_rn(t.y * inv);
        int q2 = __float2int_rn(t.z * inv);
        int q3 = __float2int_rn(t.w * inv);
        zq[i] = (int)((uint32_t)(q0 & 255) | ((uint32_t)(q1 & 255) << 8) |
                      ((uint32_t)(q2 & 255) << 16) | ((uint32_t)(q3 & 255) << 24));
        sabs += abs(q0) + abs(q1) + abs(q2) + abs(q3);
    }
    const float czp = sz * CZCONST;

    int mA1 = 0x7FFFFFFF, mA2 = 0x7FFFFFFF, mA3 = 0x7FFFFFFF, mA4 = 0x7FFFFFFF;
    int mB1 = 0x7FFFFFFF, mB2 = 0x7FFFFFFF, mB3 = 0x7FFFFFFF, mB4 = 0x7FFFFFFF;

    const uint4* wq = (const uint4*)g_wq;
    #pragma unroll 4
    for (int it = 0; it < 512; ++it) {           // 2 codes per iteration
        const uint4* wr = wq + it * 8;
        uint4 c0a = __ldg(wr + 0), c0b = __ldg(wr + 1);
        uint4 c0c = __ldg(wr + 2), c0d = __ldg(wr + 3);
        uint4 c1a = __ldg(wr + 4), c1b = __ldg(wr + 5);
        uint4 c1c = __ldg(wr + 6), c1d = __ldg(wr + 7);

        int a0 = 0, a1 = 0;
        a0 = dp4(zq[0],  (int)c0a.x, a0);  a1 = dp4(zq[0],  (int)c1a.x, a1);
        a0 = dp4(zq[1],  (int)c0a.y, a0);  a1 = dp4(zq[1],  (int)c1a.y, a1);
        a0 = dp4(zq[2],  (int)c0a.z, a0);  a1 = dp4(zq[2],  (int)c1a.z, a1);
        a0 = dp4(zq[3],  (int)c0a.w, a0);  a1 = dp4(zq[3],  (int)c1a.w, a1);
        a0 = dp4(zq[4],  (int)c0b.x, a0);  a1 = dp4(zq[4],  (int)c1b.x, a1);
        a0 = dp4(zq[5],  (int)c0b.y, a0);  a1 = dp4(zq[5],  (int)c1b.y, a1);
        a0 = dp4(zq[6],  (int)c0b.z, a0);  a1 = dp4(zq[6],  (int)c1b.z, a1);
        a0 = dp4(zq[7],  (int)c0b.w, a0);  a1 = dp4(zq[7],  (int)c1b.w, a1);
        a0 = dp4(zq[8],  (int)c0c.x, a0);  a1 = dp4(zq[8],  (int)c1c.x, a1);
        a0 = dp4(zq[9],  (int)c0c.y, a0);  a1 = dp4(zq[9],  (int)c1c.y, a1);
        a0 = dp4(zq[10], (int)c0c.z, a0);  a1 = dp4(zq[10], (int)c1c.z, a1);
        a0 = dp4(zq[11], (int)c0c.w, a0);  a1 = dp4(zq[11], (int)c1c.w, a1);
        a0 = dp4(zq[12], (int)c0d.x, a0);  a1 = dp4(zq[12], (int)c1d.x, a1);
        a0 = dp4(zq[13], (int)c0d.y, a0);  a1 = dp4(zq[13], (int)c1d.y, a1);
        a0 = dp4(zq[14], (int)c0d.z, a0);  a1 = dp4(zq[14], (int)c1d.z, a1);
        a0 = dp4(zq[15], (int)c0d.w, a0);  a1 = dp4(zq[15], (int)c1d.w, a1);

        const float2 bc = __ldg((const float2*)(g_wsC21 + it * 2));
        const int k0 = it * 2;
        int s0 = (__float2int_rn(__fmaf_rn(-czp, (float)a0, bc.x)) << 10) | k0;
        int s1 = (__float2int_rn(__fmaf_rn(-czp, (float)a1, bc.y)) << 10) | (k0 + 1);
        top4(mA1, mA2, mA3, mA4, s0);
        top4(mB1, mB2, mB3, mB4, s1);
    }

    // Sound per-token error window (counts of 2^-21):
    //   E_z = 0.5*sz*max_k||w_k||_1 ; E_w = sz*sum|zq| / (2*QW)
    //   window = 2*(E_z+E_w) + 5e-5 (covers reference-rounding + epilogue)
    const float w1max = __int_as_float(*(volatile int*)&g_w1max);
    const float Ez = 0.5f * sz * w1max;
    const float Ew = sz * (float)sabs * (0.5f / QWF);
    const int Eint = (int)ceilf((2.0f * (Ez + Ew) + 5e-5f) * TWO21 * 1.00001f);

    const int m1g  = min(mA1, mB1);
    const int base = m1g >> 10;

    if (((mA4 >> 10) - base <= Eint) || ((mB4 >> 10) - base <= Eint)) {
        // cannot certify top-4 covers the window -> exact full scan
        const int k1 = m1g & 1023;
        g_idx[tok]   = k1;
        out_idx[tok] = (float)k1;
        int p = atomicAdd(&g_flagn, 1);
        g_flags[p] = tok;
        return;
    }

    // Exact rescore (bit-exact reference chain) of in-window candidates
    float best = CUDART_INF_F;
    int   bidx = 0x7FFFFFFF;
    int cand[8] = {mA1, mA2, mA3, mA4, mB1, mB2, mB3, mB4};
    #pragma unroll
    for (int i = 0; i < 8; ++i) {
        if ((cand[i] >> 10) - base <= Eint) {
            const int k = cand[i] & 1023;
            const float4* w4 = (const float4*)(w + (size_t)k * DIM);
            float dot = 0.0f;
            #pragma unroll
            for (int j = 0; j < 16; ++j) {
                float4 zv = zp[j];
                float4 wv = __ldg(w4 + j);
                dot = __fmaf_rn(zv.x, wv.x, dot);
                dot = __fmaf_rn(zv.y, wv.y, dot);
                dot = __fmaf_rn(zv.z, wv.z, dot);
                dot = __fmaf_rn(zv.w, wv.w, dot);
            }
            float tt = __fadd_rn(a, __ldg(&g_wsum2[k]));
            float dd = __fadd_rn(tt, -__fmul_rn(2.0f, dot));
            if (dd < best || (dd == best && k < bidx)) { best = dd; bidx = k; }
        }
    }
    g_idx[tok]   = bidx;
    out_idx[tok] = (float)bidx;
}

// ---------------------------------------------------------------------------
// Exact fallback: bit-exact reference semantics for flagged tokens.
__global__ __launch_bounds__(256)
void k_exact(const float* __restrict__ z,
             const float* __restrict__ w,
             float* __restrict__ out_idx)
{
    const int lane = threadIdx.x & 31;
    const int gw   = (blockIdx.x * blockDim.x + threadIdx.x) >> 5;
    const int nw   = (gridDim.x * blockDim.x) >> 5;
    const int nflag = g_flagn;

    for (int i = gw; i < nflag; i += nw) {
        const size_t token = (size_t)g_flags[i];

        float zr[DIM];
        float a = 0.0f;
        #pragma unroll
        for (int d = 0; d < DIM; ++d) {
            zr[d] = z[token * DIM + d];
            a = __fadd_rn(a, __fmul_rn(zr[d], zr[d]));
        }

        float best = CUDART_INF_F;
        int   bidx = 0;

        for (int k0 = lane; k0 < KCODE; k0 += 128) {
            const float* w0 = w + (size_t)(k0 +  0) * DIM;
            const float* w1 = w + (size_t)(k0 + 32) * DIM;
            const float* w2 = w + (size_t)(k0 + 64) * DIM;
            const float* w3 = w + (size_t)(k0 + 96) * DIM;
            float d0 = 0.0f, d1 = 0.0f, d2 = 0.0f, d3 = 0.0f;
            #pragma unroll
            for (int d = 0; d < DIM; ++d) {
                const float zv = zr[d];
                d0 = __fmaf_rn(zv, w0[d], d0);
                d1 = __fmaf_rn(zv, w1[d], d1);
                d2 = __fmaf_rn(zv, w2[d], d2);
                d3 = __fmaf_rn(zv, w3[d], d3);
            }
            float tt, dd;
            tt = __fadd_rn(a, g_wsum2[k0]);
            dd = __fadd_rn(tt, -__fmul_rn(2.0f, d0));
            if (dd < best) { best = dd; bidx = k0; }
            tt = __fadd_rn(a, g_wsum2[k0 + 32]);
            dd = __fadd_rn(tt, -__fmul_rn(2.0f, d1));
            if (dd < best) { best = dd; bidx = k0 + 32; }
            tt = __fadd_rn(a, g_wsum2[k0 + 64]);
            dd = __fadd_rn(tt, -__fmul_rn(2.0f, d2));
            if (dd < best) { best = dd; bidx = k0 + 64; }
            tt = __fadd_rn(a, g_wsum2[k0 + 96]);
            dd = __fadd_rn(tt, -__fmul_rn(2.0f, d3));
            if (dd < best) { best = dd; bidx = k0 + 96; }
        }

        #pragma unroll
        for (int off = 16; off > 0; off >>= 1) {
            float ov = __shfl_down_sync(0xffffffffu, best, off);
            int   oi = __shfl_down_sync(0xffffffffu, bidx, off);
            if (ov < best || (ov == best && oi < bidx)) { best = ov; bidx = oi; }
        }
        if (lane == 0) {
            g_idx[token]   = bidx;
            out_idx[token] = (float)bidx;
        }
    }
}

// ---------------------------------------------------------------------------
// Gather z_q_st = fl(z + fl(w[idx] - z)); per-block double partial (no atomic).
__global__ __launch_bounds__(512)
void k_gather(const float* __restrict__ z,
              const float* __restrict__ w,
              float* __restrict__ out_zq)
{
    __shared__ double sred[16];
    const int tid = threadIdx.x;
    const size_t token = (size_t)blockIdx.x * 32 + (tid >> 4);
    const int c = tid & 15;

    const int idx = g_idx[token];
    const float4 wv = ((const float4*)(w + (size_t)idx * DIM))[c];
    const float4 zv = ((const float4*)(z + token * DIM))[c];

    const float dx = __fsub_rn(wv.x, zv.x);
    const float dy = __fsub_rn(wv.y, zv.y);
    const float dz = __fsub_rn(wv.z, zv.z);
    const float dw = __fsub_rn(wv.w, zv.w);

    float4 o;
    o.x = __fadd_rn(zv.x, dx);
    o.y = __fadd_rn(zv.y, dy);
    o.z = __fadd_rn(zv.z, dz);
    o.w = __fadd_rn(zv.w, dw);
    ((float4*)out_zq)[token * (DIM / 4) + c] = o;

    double s = (double)__fmul_rn(dx, dx);
    s += (double)__fmul_rn(dy, dy);
    s += (double)__fmul_rn(dz, dz);
    s += (double)__fmul_rn(dw, dw);

    #pragma unroll
    for (int off = 16; off > 0; off >>= 1)
        s += __shfl_down_sync(0xffffffffu, s, off);

    const int wrp = tid >> 5;
    if ((tid & 31) == 0) sred[wrp] = s;
    __syncthreads();

    if (wrp == 0) {
        double v = (tid < 16) ? sred[tid] : 0.0;
        #pragma unroll
        for (int off = 8; off > 0; off >>= 1)
            v += __shfl_down_sync(0xffffffffu, v, off);
        if (tid == 0) g_part[blockIdx.x] = v;
    }
}

// ---------------------------------------------------------------------------
__global__ __launch_bounds__(256)
void k_final(float* __restrict__ out_loss, int total_elems)
{
    __shared__ double sm[8];
    const int tid = threadIdx.x;
    double s = 0.0;
    for (int i = tid; i < NPART; i += 256) s += g_part[i];
    #pragma unroll
    for (int off = 16; off > 0; off >>= 1)
        s += __shfl_down_sync(0xffffffffu, s, off);
    if ((tid & 31) == 0) sm[tid >> 5] = s;
    __syncthreads();
    if (tid == 0) {
        double tot = 0.0;
        #pragma unroll
        for (int i = 0; i < 8; ++i) tot += sm[i];
        const float m = (float)(tot / (double)total_elems);
        out_loss[0] = __fadd_rn(m, __fmul_rn(0.25f, m));
    }
}

// ---------------------------------------------------------------------------
extern "C" void kernel_launch(void* const* d_in, const int* in_sizes, int n_in,
                              void* d_out, int out_size)
{
    const float* z = (const float*)d_in[0];   // (N, 64) fp32
    const float* w = (const float*)d_in[1];   // (1024, 64) fp32

    const int ND = in_sizes[0];
    const int N  = ND / DIM;                  // 262144

    float* out      = (float*)d_out;
    float* out_zq   = out;                    // N*64 floats
    float* out_loss = out + (size_t)N * DIM;  // 1 float
    float* out_idx  = out_loss + 1;           // N floats

    k_prep_w<<<KCODE / 128, 256>>>(w);
    k_filter<<<N / 256, 256>>>(z, w, out_idx);
    k_exact<<<256, 256>>>(z, w, out_idx);
    k_gather<<<N / 32, 512>>>(z, w, out_zq);
    k_final<<<1, 256>>>(out_loss, ND);
}

// round 16
// speedup vs baseline: 1.6718x; 1.2645x over previous
#include <cuda_runtime.h>
#include <math_constants.h>
#include <cstdint>

#define DIM     64
#define KCODE   1024
#define MAXN    262144
#define NPART   2048

#define QWF     130048.0f            // w int8 scale: 1024*127
#define TWO21   2097152.0f
#define CZCONST (2.0f * 2097152.0f / 130048.0f)   // 2*2^21/QW

// ---------------------------------------------------------------------------
// Device scratch (no cudaMalloc allowed)
__device__ int       g_idx[MAXN];
__device__ float     g_wsum2[KCODE];    // exact sequential-chain ||w||^2
__device__ float     g_wsC21[KCODE];    // fl(fl(||w||^2 + 0.25) * 2^21)
__device__ int       g_flagn;
__device__ int       g_flags[MAXN];
__device__ double    g_part[NPART];     // [0,1024): filter CTAs, [1024,2048): exact CTAs
__device__ int       g_w1max;           // max_k ||w_k||_1 as float-bits (atomicMax)
__device__ uint32_t  g_wq[KCODE * 16];  // per code: 64 int8 packed in 16 u32

// ---------------------------------------------------------------------------
__device__ __forceinline__ int dp4(int a, int b, int c) {
    int r;
    asm("dp4a.s32.s32 %0, %1, %2, %3;" : "=r"(r) : "r"(a), "r"(b), "r"(c));
    return r;
}
__device__ __forceinline__ void top4(int& m1, int& m2, int& m3, int& m4, int s) {
    int t1 = max(m1, s); m1 = min(m1, s);
    int t2 = max(m2, t1); m2 = min(m2, t1);
    int t3 = max(m3, t2); m3 = min(m3, t2);
    m4 = min(m4, t3);
}

// ---------------------------------------------------------------------------
// Codebook prep + zero g_part/g_flagn. Grid 8 x 256.
__global__ __launch_bounds__(256, 1)
void k_prep_w(const float* __restrict__ w)
{
    __shared__ __align__(16) float sw[128 * DIM];   // 32KB
    const int tid = threadIdx.x;
    const int k0  = blockIdx.x * 128;

    if (blockIdx.x == 0 && tid == 0) g_flagn = 0;
    g_part[blockIdx.x * 256 + tid] = 0.0;           // 2048 slots, one each

    {   // coalesced stage: 2048 float4
        const float4* src = (const float4*)(w + (size_t)k0 * DIM);
        float4* dst = (float4*)sw;
        #pragma unroll
        for (int i = 0; i < 8; ++i) dst[tid + i * 256] = src[tid + i * 256];
    }
    __syncthreads();

    if (tid < 128) {
        const float* r = sw + tid * DIM;
        const int k = k0 + tid;
        float s = 0.0f;
        #pragma unroll
        for (int d = 0; d < DIM; ++d)
            s = __fadd_rn(s, __fmul_rn(r[d], r[d]));
        g_wsum2[k] = s;
        g_wsC21[k] = __fmul_rn(__fadd_rn(s, 0.25f), TWO21);

        float w1 = 0.0f;
        #pragma unroll
        for (int d = 0; d < DIM; ++d) w1 += fabsf(r[d]);
        atomicMax(&g_w1max, __float_as_int(w1 * 1.000002f));

        #pragma unroll
        for (int j = 0; j < 16; ++j) {
            int q0 = __float2int_rn(r[4 * j + 0] * QWF);
            int q1 = __float2int_rn(r[4 * j + 1] * QWF);
            int q2 = __float2int_rn(r[4 * j + 2] * QWF);
            int q3 = __float2int_rn(r[4 * j + 3] * QWF);
            g_wq[(size_t)k * 16 + j] =
                (uint32_t)(q0 & 255) | ((uint32_t)(q1 & 255) << 8) |
                ((uint32_t)(q2 & 255) << 16) | ((uint32_t)(q3 & 255) << 24);
        }
    }
}

// ---------------------------------------------------------------------------
// dp4a filter + certificate + exact rescore + FUSED gather/loss for certified
// tokens. Flagged tokens (uncertifiable) go to k_exact2.
__global__ __launch_bounds__(256)
void k_filter(const float* __restrict__ z,
              const float* __restrict__ w,
              float* __restrict__ out_zq,
              float* __restrict__ out_idx)
{
    __shared__ double sred[8];
    const int tid = threadIdx.x;
    const int tok = blockIdx.x * 256 + tid;
    const float4* zp = (const float4*)(z + (size_t)tok * DIM);

    // Pass 1: zmax + exact sequential ||z||^2 chain (reference order)
    float a = 0.0f, zm = 0.0f;
    #pragma unroll
    for (int i = 0; i < 16; ++i) {
        float4 t = zp[i];
        a = __fadd_rn(a, __fmul_rn(t.x, t.x));
        a = __fadd_rn(a, __fmul_rn(t.y, t.y));
        a = __fadd_rn(a, __fmul_rn(t.z, t.z));
        a = __fadd_rn(a, __fmul_rn(t.w, t.w));
        zm = fmaxf(zm, fmaxf(fmaxf(fabsf(t.x), fabsf(t.y)),
                             fmaxf(fabsf(t.z), fabsf(t.w))));
    }
    const float inv = (zm > 0.0f) ? (127.0f / zm) : 0.0f;
    const float sz  = zm * (1.0f / 127.0f);

    // Pass 2: quantize z
    int zq[16];
    int sabs = 0;
    #pragma unroll
    for (int i = 0; i < 16; ++i) {
        float4 t = zp[i];
        int q0 = __float2int_rn(t.x * inv);
        int q1 = __float2int_rn(t.y * inv);
        int q2 = __float2int_rn(t.z * inv);
        int q3 = __float2int_rn(t.w * inv);
        zq[i] = (int)((uint32_t)(q0 & 255) | ((uint32_t)(q1 & 255) << 8) |
                      ((uint32_t)(q2 & 255) << 16) | ((uint32_t)(q3 & 255) << 24));
        sabs += abs(q0) + abs(q1) + abs(q2) + abs(q3);
    }
    const float czp = sz * CZCONST;

    int mA1 = 0x7FFFFFFF, mA2 = 0x7FFFFFFF, mA3 = 0x7FFFFFFF, mA4 = 0x7FFFFFFF;
    int mB1 = 0x7FFFFFFF, mB2 = 0x7FFFFFFF, mB3 = 0x7FFFFFFF, mB4 = 0x7FFFFFFF;

    const uint4* wq = (const uint4*)g_wq;
    #pragma unroll 4
    for (int it = 0; it < 512; ++it) {           // 2 codes per iteration
        const uint4* wr = wq + it * 8;
        uint4 c0a = __ldg(wr + 0), c0b = __ldg(wr + 1);
        uint4 c0c = __ldg(wr + 2), c0d = __ldg(wr + 3);
        uint4 c1a = __ldg(wr + 4), c1b = __ldg(wr + 5);
        uint4 c1c = __ldg(wr + 6), c1d = __ldg(wr + 7);

        int a0 = 0, a1 = 0;
        a0 = dp4(zq[0],  (int)c0a.x, a0);  a1 = dp4(zq[0],  (int)c1a.x, a1);
        a0 = dp4(zq[1],  (int)c0a.y, a0);  a1 = dp4(zq[1],  (int)c1a.y, a1);
        a0 = dp4(zq[2],  (int)c0a.z, a0);  a1 = dp4(zq[2],  (int)c1a.z, a1);
        a0 = dp4(zq[3],  (int)c0a.w, a0);  a1 = dp4(zq[3],  (int)c1a.w, a1);
        a0 = dp4(zq[4],  (int)c0b.x, a0);  a1 = dp4(zq[4],  (int)c1b.x, a1);
        a0 = dp4(zq[5],  (int)c0b.y, a0);  a1 = dp4(zq[5],  (int)c1b.y, a1);
        a0 = dp4(zq[6],  (int)c0b.z, a0);  a1 = dp4(zq[6],  (int)c1b.z, a1);
        a0 = dp4(zq[7],  (int)c0b.w, a0);  a1 = dp4(zq[7],  (int)c1b.w, a1);
        a0 = dp4(zq[8],  (int)c0c.x, a0);  a1 = dp4(zq[8],  (int)c1c.x, a1);
        a0 = dp4(zq[9],  (int)c0c.y, a0);  a1 = dp4(zq[9],  (int)c1c.y, a1);
        a0 = dp4(zq[10], (int)c0c.z, a0);  a1 = dp4(zq[10], (int)c1c.z, a1);
        a0 = dp4(zq[11], (int)c0c.w, a0);  a1 = dp4(zq[11], (int)c1c.w, a1);
        a0 = dp4(zq[12], (int)c0d.x, a0);  a1 = dp4(zq[12], (int)c1d.x, a1);
        a0 = dp4(zq[13], (int)c0d.y, a0);  a1 = dp4(zq[13], (int)c1d.y, a1);
        a0 = dp4(zq[14], (int)c0d.z, a0);  a1 = dp4(zq[14], (int)c1d.z, a1);
        a0 = dp4(zq[15], (int)c0d.w, a0);  a1 = dp4(zq[15], (int)c1d.w, a1);

        const float2 bc = __ldg((const float2*)(g_wsC21 + it * 2));
        const int k0 = it * 2;
        int s0 = (__float2int_rn(__fmaf_rn(-czp, (float)a0, bc.x)) << 10) | k0;
        int s1 = (__float2int_rn(__fmaf_rn(-czp, (float)a1, bc.y)) << 10) | (k0 + 1);
        top4(mA1, mA2, mA3, mA4, s0);
        top4(mB1, mB2, mB3, mB4, s1);
    }

    // Sound per-token error window
    const float w1max = __int_as_float(*(volatile int*)&g_w1max);
    const float Ez = 0.5f * sz * w1max;
    const float Ew = sz * (float)sabs * (0.5f / QWF);
    const int Eint = (int)ceilf((2.0f * (Ez + Ew) + 5e-5f) * TWO21 * 1.00001f);

    const int m1g  = min(mA1, mB1);
    const int base = m1g >> 10;

    const bool flagged = ((mA4 >> 10) - base <= Eint) ||
                         ((mB4 >> 10) - base <= Eint);

    int bidx;
    if (flagged) {
        bidx = m1g & 1023;                 // provisional; k_exact2 overwrites
        int p = atomicAdd(&g_flagn, 1);
        g_flags[p] = tok;
    } else {
        // Exact rescore (bit-exact reference chain) of in-window candidates
        float best = CUDART_INF_F;
        bidx = 0x7FFFFFFF;
        int cand[8] = {mA1, mA2, mA3, mA4, mB1, mB2, mB3, mB4};
        #pragma unroll
        for (int i = 0; i < 8; ++i) {
            if ((cand[i] >> 10) - base <= Eint) {
                const int k = cand[i] & 1023;
                const float4* w4 = (const float4*)(w + (size_t)k * DIM);
                float dot = 0.0f;
                #pragma unroll
                for (int j = 0; j < 16; ++j) {
                    float4 zv = zp[j];
                    float4 wv = __ldg(w4 + j);
                    dot = __fmaf_rn(zv.x, wv.x, dot);
                    dot = __fmaf_rn(zv.y, wv.y, dot);
                    dot = __fmaf_rn(zv.z, wv.z, dot);
                    dot = __fmaf_rn(zv.w, wv.w, dot);
                }
                float tt = __fadd_rn(a, __ldg(&g_wsum2[k]));
                float dd = __fadd_rn(tt, -__fmul_rn(2.0f, dot));
                if (dd < best || (dd == best && k < bidx)) { best = dd; bidx = k; }
            }
        }
    }
    g_idx[tok]   = bidx;
    out_idx[tok] = (float)bidx;

    // Fused gather + loss for certified tokens (flagged handled by k_exact2)
    double accd = 0.0;
    if (!flagged) {
        const float4* wrow = (const float4*)(w + (size_t)bidx * DIM);
        float4* orow = (float4*)(out_zq + (size_t)tok * DIM);
        #pragma unroll
        for (int j = 0; j < 16; ++j) {
            float4 zv = zp[j];
            float4 wv = __ldg(wrow + j);
            const float dx = __fsub_rn(wv.x, zv.x);
            const float dy = __fsub_rn(wv.y, zv.y);
            const float dz = __fsub_rn(wv.z, zv.z);
            const float dw = __fsub_rn(wv.w, zv.w);
            float4 o;
            o.x = __fadd_rn(zv.x, dx);
            o.y = __fadd_rn(zv.y, dy);
            o.z = __fadd_rn(zv.z, dz);
            o.w = __fadd_rn(zv.w, dw);
            orow[j] = o;
            accd += (double)__fmul_rn(dx, dx);
            accd += (double)__fmul_rn(dy, dy);
            accd += (double)__fmul_rn(dz, dz);
            accd += (double)__fmul_rn(dw, dw);
        }
    }
    #pragma unroll
    for (int off = 16; off > 0; off >>= 1)
        accd += __shfl_down_sync(0xffffffffu, accd, off);
    if ((tid & 31) == 0) sred[tid >> 5] = accd;
    __syncthreads();
    if (tid == 0) {
        double v = 0.0;
        #pragma unroll
        for (int i = 0; i < 8; ++i) v += sred[i];
        g_part[blockIdx.x] = v;
    }
}

// ---------------------------------------------------------------------------
// Exact fallback, R2-style (fma-bound): 256 flagged tokens per CTA, smem
// 32-code tiles, bit-exact sequential chains. Also does gather + loss.
__global__ __launch_bounds__(256)
void k_exact2(const float* __restrict__ z,
              const float* __restrict__ w,
              float* __restrict__ out_zq,
              float* __restrict__ out_idx)
{
    const int nflag = g_flagn;
    if (blockIdx.x * 256 >= nflag) return;      // uniform early-out

    __shared__ __align__(16) float sW[32 * DIM];   // 8KB code tile
    __shared__ float  sB[32];
    __shared__ double sred[8];

    const int tid = threadIdx.x;
    const int i   = blockIdx.x * 256 + tid;
    const bool active = (i < nflag);
    const int token = active ? g_flags[i] : g_flags[0];

    // z row -> registers + exact sequential a-chain
    float zr[DIM];
    float a = 0.0f;
    {
        const float4* zsrc = (const float4*)(z + (size_t)token * DIM);
        #pragma unroll
        for (int q = 0; q < 16; ++q) {
            float4 v = zsrc[q];
            zr[4 * q + 0] = v.x; zr[4 * q + 1] = v.y;
            zr[4 * q + 2] = v.z; zr[4 * q + 3] = v.w;
        }
        #pragma unroll
        for (int d = 0; d < DIM; ++d)
            a = __fadd_rn(a, __fmul_rn(zr[d], zr[d]));
    }

    float best = CUDART_INF_F;
    int   bidx = 0;

    for (int kt = 0; kt < KCODE / 32; ++kt) {
        __syncthreads();
        {   // stage 32x64 tile: 512 float4 / 256 threads
            const float4* wsrc = (const float4*)(w + (size_t)kt * 32 * DIM);
            float4* wdst = (float4*)sW;
            wdst[tid]       = wsrc[tid];
            wdst[tid + 256] = wsrc[tid + 256];
            if (tid < 32) sB[tid] = g_wsum2[kt * 32 + tid];
        }
        __syncthreads();

        #pragma unroll 1
        for (int k = 0; k < 32; k += 4) {
            const float* w0 = sW + (k + 0) * DIM;
            const float* w1 = sW + (k + 1) * DIM;
            const float* w2 = sW + (k + 2) * DIM;
            const float* w3 = sW + (k + 3) * DIM;
            float d0 = 0.0f, d1 = 0.0f, d2 = 0.0f, d3 = 0.0f;
            #pragma unroll
            for (int d = 0; d < DIM; ++d) {
                const float zv = zr[d];
                d0 = __fmaf_rn(zv, w0[d], d0);
                d1 = __fmaf_rn(zv, w1[d], d1);
                d2 = __fmaf_rn(zv, w2[d], d2);
                d3 = __fmaf_rn(zv, w3[d], d3);
            }
            const int kb = kt * 32 + k;
            float t, dd;
            t  = __fadd_rn(a, sB[k + 0]);
            dd = __fadd_rn(t, -__fmul_rn(2.0f, d0));
            if (dd < best) { best = dd; bidx = kb + 0; }
            t  = __fadd_rn(a, sB[k + 1]);
            dd = __fadd_rn(t, -__fmul_rn(2.0f, d1));
            if (dd < best) { best = dd; bidx = kb + 1; }
            t  = __fadd_rn(a, sB[k + 2]);
            dd = __fadd_rn(t, -__fmul_rn(2.0f, d2));
            if (dd < best) { best = dd; bidx = kb + 2; }
            t  = __fadd_rn(a, sB[k + 3]);
            dd = __fadd_rn(t, -__fmul_rn(2.0f, d3));
            if (dd < best) { best = dd; bidx = kb + 3; }
        }
    }

    // gather + loss for this flagged token
    double accd = 0.0;
    if (active) {
        g_idx[token]   = bidx;
        out_idx[token] = (float)bidx;
        const float4* wrow = (const float4*)(w + (size_t)bidx * DIM);
        float4* orow = (float4*)(out_zq + (size_t)token * DIM);
        #pragma unroll
        for (int j = 0; j < 16; ++j) {
            float4 wv = __ldg(wrow + j);
            const float zx = zr[4 * j + 0], zy = zr[4 * j + 1];
            const float zz = zr[4 * j + 2], zw = zr[4 * j + 3];
            const float dx = __fsub_rn(wv.x, zx);
            const float dy = __fsub_rn(wv.y, zy);
            const float dz = __fsub_rn(wv.z, zz);
            const float dw = __fsub_rn(wv.w, zw);
            float4 o;
            o.x = __fadd_rn(zx, dx);
            o.y = __fadd_rn(zy, dy);
            o.z = __fadd_rn(zz, dz);
            o.w = __fadd_rn(zw, dw);
            orow[j] = o;
            accd += (double)__fmul_rn(dx, dx);
            accd += (double)__fmul_rn(dy, dy);
            accd += (double)__fmul_rn(dz, dz);
            accd += (double)__fmul_rn(dw, dw);
        }
    }
    #pragma unroll
    for (int off = 16; off > 0; off >>= 1)
        accd += __shfl_down_sync(0xffffffffu, accd, off);
    if ((tid & 31) == 0) sred[tid >> 5] = accd;
    __syncthreads();
    if (tid == 0) {
        double v = 0.0;
        #pragma unroll
        for (int j = 0; j < 8; ++j) v += sred[j];
        g_part[1024 + blockIdx.x] = v;
    }
}

// ---------------------------------------------------------------------------
__global__ __launch_bounds__(256)
void k_final(float* __restrict__ out_loss, int total_elems)
{
    __shared__ double sm[8];
    const int tid = threadIdx.x;
    double s = 0.0;
    for (int i = tid; i < NPART; i += 256) s += g_part[i];
    #pragma unroll
    for (int off = 16; off > 0; off >>= 1)
        s += __shfl_down_sync(0xffffffffu, s, off);
    if ((tid & 31) == 0) sm[tid >> 5] = s;
    __syncthreads();
    if (tid == 0) {
        double tot = 0.0;
        #pragma unroll
        for (int i = 0; i < 8; ++i) tot += sm[i];
        const float m = (float)(tot / (double)total_elems);
        out_loss[0] = __fadd_rn(m, __fmul_rn(0.25f, m));
    }
}

// ---------------------------------------------------------------------------
extern "C" void kernel_launch(void* const* d_in, const int* in_sizes, int n_in,
                              void* d_out, int out_size)
{
    const float* z = (const float*)d_in[0];   // (N, 64) fp32
    const float* w = (const float*)d_in[1];   // (1024, 64) fp32

    const int ND = in_sizes[0];
    const int N  = ND / DIM;                  // 262144

    float* out      = (float*)d_out;
    float* out_zq   = out;                    // N*64 floats
    float* out_loss = out + (size_t)N * DIM;  // 1 float
    float* out_idx  = out_loss + 1;           // N floats

    k_prep_w<<<8, 256>>>(w);
    k_filter<<<N / 256, 256>>>(z, w, out_zq, out_idx);
    k_exact2<<<N / 256, 256>>>(z, w, out_zq, out_idx);
    k_final<<<1, 256>>>(out_loss, ND);
}

// round 17
// speedup vs baseline: 2.4110x; 1.4422x over previous
#include <cuda_runtime.h>
#include <math_constants.h>
#include <cstdint>

#define DIM     64
#define KCODE   1024
#define MAXN    262144
#define NPART   2048

#define QWF     130048.0f            // w int8 scale: 1024*127
#define TWO21   2097152.0f
#define CZCONST (2.0f * 2097152.0f / 130048.0f)   // 2*2^21/QW

// ---------------------------------------------------------------------------
// Device scratch (no cudaMalloc allowed)
__device__ int       g_idx[MAXN];
__device__ float     g_wsum2[KCODE];    // exact sequential-chain ||w||^2
__device__ float     g_wsC21[KCODE];    // fl(fl(||w||^2 + 0.25) * 2^21)
__device__ int       g_flagn;
__device__ int       g_flags[MAXN];
__device__ double    g_part[NPART];     // [0,256): filter CTAs, [1024,2048): exact CTAs
__device__ int       g_w1max;           // max_k ||w_k||_1 as float-bits (atomicMax)
__device__ uint32_t  g_wq[KCODE * 16];  // per code: 64 int8 packed in 16 u32

// ---------------------------------------------------------------------------
__device__ __forceinline__ int dp4(int a, int b, int c) {
    int r;
    asm("dp4a.s32.s32 %0, %1, %2, %3;" : "=r"(r) : "r"(a), "r"(b), "r"(c));
    return r;
}
__device__ __forceinline__ void top4(int& m1, int& m2, int& m3, int& m4, int s) {
    int t1 = max(m1, s); m1 = min(m1, s);
    int t2 = max(m2, t1); m2 = min(m2, t1);
    int t3 = max(m3, t2); m3 = min(m3, t2);
    m4 = min(m4, t3);
}

// ---------------------------------------------------------------------------
// Codebook prep + zero g_part/g_flagn. Grid 8 x 256.
__global__ __launch_bounds__(256, 1)
void k_prep_w(const float* __restrict__ w)
{
    __shared__ __align__(16) float sw[128 * DIM];   // 32KB
    const int tid = threadIdx.x;
    const int k0  = blockIdx.x * 128;

    if (blockIdx.x == 0 && tid == 0) g_flagn = 0;
    g_part[blockIdx.x * 256 + tid] = 0.0;           // 2048 slots, one each

    {   // coalesced stage: 2048 float4
        const float4* src = (const float4*)(w + (size_t)k0 * DIM);
        float4* dst = (float4*)sw;
        #pragma unroll
        for (int i = 0; i < 8; ++i) dst[tid + i * 256] = src[tid + i * 256];
    }
    __syncthreads();

    if (tid < 128) {
        const float* r = sw + tid * DIM;
        const int k = k0 + tid;
        float s = 0.0f;
        #pragma unroll
        for (int d = 0; d < DIM; ++d)
            s = __fadd_rn(s, __fmul_rn(r[d], r[d]));
        g_wsum2[k] = s;
        g_wsC21[k] = __fmul_rn(__fadd_rn(s, 0.25f), TWO21);

        float w1 = 0.0f;
        #pragma unroll
        for (int d = 0; d < DIM; ++d) w1 += fabsf(r[d]);
        atomicMax(&g_w1max, __float_as_int(w1 * 1.000002f));

        #pragma unroll
        for (int j = 0; j < 16; ++j) {
            int q0 = __float2int_rn(r[4 * j + 0] * QWF);
            int q1 = __float2int_rn(r[4 * j + 1] * QWF);
            int q2 = __float2int_rn(r[4 * j + 2] * QWF);
            int q3 = __float2int_rn(r[4 * j + 3] * QWF);
            g_wq[(size_t)k * 16 + j] =
                (uint32_t)(q0 & 255) | ((uint32_t)(q1 & 255) << 8) |
                ((uint32_t)(q2 & 255) << 16) | ((uint32_t)(q3 & 255) << 24);
        }
    }
}

// ---------------------------------------------------------------------------
// dp4a filter, 4 tokens per thread (register-blocked): each loaded code feeds
// 64 dp4a. Certificate + exact rescore + fused gather/loss for certified
// tokens; uncertifiable tokens flagged for k_exact2.
__global__ __launch_bounds__(256, 1)
void k_filter(const float* __restrict__ z,
              const float* __restrict__ w,
              float* __restrict__ out_zq,
              float* __restrict__ out_idx)
{
    __shared__ double sred[8];
    const int tid  = threadIdx.x;
    const int tokb = blockIdx.x * 1024 + tid;   // tokens tokb + j*256

    float a[4], czp[4], szv[4];
    int   sabs[4];
    int   zq[4][16];

    // Pass 1+2 per token: exact ||z||^2 chain, zmax, int8 quantization
    #pragma unroll
    for (int j = 0; j < 4; ++j) {
        const float4* zp = (const float4*)(z + (size_t)(tokb + j * 256) * DIM);
        float aa = 0.0f, zm = 0.0f;
        #pragma unroll
        for (int i = 0; i < 16; ++i) {
            float4 t = zp[i];
            aa = __fadd_rn(aa, __fmul_rn(t.x, t.x));
            aa = __fadd_rn(aa, __fmul_rn(t.y, t.y));
            aa = __fadd_rn(aa, __fmul_rn(t.z, t.z));
            aa = __fadd_rn(aa, __fmul_rn(t.w, t.w));
            zm = fmaxf(zm, fmaxf(fmaxf(fabsf(t.x), fabsf(t.y)),
                                 fmaxf(fabsf(t.z), fabsf(t.w))));
        }
        a[j]   = aa;
        szv[j] = zm * (1.0f / 127.0f);
        const float inv = (zm > 0.0f) ? (127.0f / zm) : 0.0f;
        int sa = 0;
        #pragma unroll
        for (int i = 0; i < 16; ++i) {
            float4 t = zp[i];
            int q0 = __float2int_rn(t.x * inv);
            int q1 = __float2int_rn(t.y * inv);
            int q2 = __float2int_rn(t.z * inv);
            int q3 = __float2int_rn(t.w * inv);
            zq[j][i] = (int)((uint32_t)(q0 & 255) | ((uint32_t)(q1 & 255) << 8) |
                             ((uint32_t)(q2 & 255) << 16) | ((uint32_t)(q3 & 255) << 24));
            sa += abs(q0) + abs(q1) + abs(q2) + abs(q3);
        }
        sabs[j] = sa;
        czp[j]  = szv[j] * CZCONST;
    }

    int m1[4], m2[4], m3[4], m4[4];
    #pragma unroll
    for (int j = 0; j < 4; ++j) {
        m1[j] = 0x7FFFFFFF; m2[j] = 0x7FFFFFFF;
        m3[j] = 0x7FFFFFFF; m4[j] = 0x7FFFFFFF;
    }

    // Main loop: one code per iteration, reused across 4 tokens
    const uint4* wq = (const uint4*)g_wq;
    #pragma unroll 2
    for (int k = 0; k < KCODE; ++k) {
        const uint4 ca = __ldg(wq + k * 4 + 0);
        const uint4 cb = __ldg(wq + k * 4 + 1);
        const uint4 cc = __ldg(wq + k * 4 + 2);
        const uint4 cd = __ldg(wq + k * 4 + 3);
        const float bc = __ldg(g_wsC21 + k);

        #pragma unroll
        for (int j = 0; j < 4; ++j) {
            int acc = 0;
            acc = dp4(zq[j][0],  (int)ca.x, acc);
            acc = dp4(zq[j][1],  (int)ca.y, acc);
            acc = dp4(zq[j][2],  (int)ca.z, acc);
            acc = dp4(zq[j][3],  (int)ca.w, acc);
            acc = dp4(zq[j][4],  (int)cb.x, acc);
            acc = dp4(zq[j][5],  (int)cb.y, acc);
            acc = dp4(zq[j][6],  (int)cb.z, acc);
            acc = dp4(zq[j][7],  (int)cb.w, acc);
            acc = dp4(zq[j][8],  (int)cc.x, acc);
            acc = dp4(zq[j][9],  (int)cc.y, acc);
            acc = dp4(zq[j][10], (int)cc.z, acc);
            acc = dp4(zq[j][11], (int)cc.w, acc);
            acc = dp4(zq[j][12], (int)cd.x, acc);
            acc = dp4(zq[j][13], (int)cd.y, acc);
            acc = dp4(zq[j][14], (int)cd.z, acc);
            acc = dp4(zq[j][15], (int)cd.w, acc);
            int s = (__float2int_rn(__fmaf_rn(-czp[j], (float)acc, bc)) << 10) | k;
            top4(m1[j], m2[j], m3[j], m4[j], s);
        }
    }

    // Per-token: certificate, rescore, gather, loss
    const float w1max = __int_as_float(*(volatile int*)&g_w1max);
    double accd = 0.0;

    #pragma unroll 1
    for (int j = 0; j < 4; ++j) {
        const int tok = tokb + j * 256;
        const float4* zp = (const float4*)(z + (size_t)tok * DIM);

        const float Ez = 0.5f * szv[j] * w1max;
        const float Ew = szv[j] * (float)sabs[j] * (0.5f / QWF);
        const int Eint = (int)ceilf((2.0f * (Ez + Ew) + 5e-5f) * TWO21 * 1.00001f);
        const int base = m1[j] >> 10;
        const bool flagged = ((m4[j] >> 10) - base <= Eint);

        int bidx;
        if (flagged) {
            bidx = m1[j] & 1023;           // provisional; k_exact2 overwrites
            int p = atomicAdd(&g_flagn, 1);
            g_flags[p] = tok;
        } else {
            float best = CUDART_INF_F;
            bidx = 0x7FFFFFFF;
            int cand[4] = {m1[j], m2[j], m3[j], m4[j]};
            #pragma unroll
            for (int i = 0; i < 4; ++i) {
                if ((cand[i] >> 10) - base <= Eint) {
                    const int k = cand[i] & 1023;
                    const float4* w4 = (const float4*)(w + (size_t)k * DIM);
                    float dot = 0.0f;
                    #pragma unroll
                    for (int q = 0; q < 16; ++q) {
                        float4 zv = zp[q];
                        float4 wv = __ldg(w4 + q);
                        dot = __fmaf_rn(zv.x, wv.x, dot);
                        dot = __fmaf_rn(zv.y, wv.y, dot);
                        dot = __fmaf_rn(zv.z, wv.z, dot);
                        dot = __fmaf_rn(zv.w, wv.w, dot);
                    }
                    float tt = __fadd_rn(a[j], __ldg(&g_wsum2[k]));
                    float dd = __fadd_rn(tt, -__fmul_rn(2.0f, dot));
                    if (dd < best || (dd == best && k < bidx)) { best = dd; bidx = k; }
                }
            }
        }
        g_idx[tok]   = bidx;
        out_idx[tok] = (float)bidx;

        if (!flagged) {
            const float4* wrow = (const float4*)(w + (size_t)bidx * DIM);
            float4* orow = (float4*)(out_zq + (size_t)tok * DIM);
            #pragma unroll
            for (int q = 0; q < 16; ++q) {
                float4 zv = zp[q];
                float4 wv = __ldg(wrow + q);
                const float dx = __fsub_rn(wv.x, zv.x);
                const float dy = __fsub_rn(wv.y, zv.y);
                const float dz = __fsub_rn(wv.z, zv.z);
                const float dw = __fsub_rn(wv.w, zv.w);
                float4 o;
                o.x = __fadd_rn(zv.x, dx);
                o.y = __fadd_rn(zv.y, dy);
                o.z = __fadd_rn(zv.z, dz);
                o.w = __fadd_rn(zv.w, dw);
                orow[q] = o;
                accd += (double)__fmul_rn(dx, dx);
                accd += (double)__fmul_rn(dy, dy);
                accd += (double)__fmul_rn(dz, dz);
                accd += (double)__fmul_rn(dw, dw);
            }
        }
    }

    #pragma unroll
    for (int off = 16; off > 0; off >>= 1)
        accd += __shfl_down_sync(0xffffffffu, accd, off);
    if ((tid & 31) == 0) sred[tid >> 5] = accd;
    __syncthreads();
    if (tid == 0) {
        double v = 0.0;
        #pragma unroll
        for (int i = 0; i < 8; ++i) v += sred[i];
        g_part[blockIdx.x] = v;
    }
}

// ---------------------------------------------------------------------------
// Exact fallback, fma-bound: 256 flagged tokens per CTA, smem 32-code tiles,
// bit-exact sequential chains. Also does gather + loss for its tokens.
__global__ __launch_bounds__(256)
void k_exact2(const float* __restrict__ z,
              const float* __restrict__ w,
              float* __restrict__ out_zq,
              float* __restrict__ out_idx)
{
    const int nflag = g_flagn;
    if (blockIdx.x * 256 >= nflag) return;      // uniform early-out

    __shared__ __align__(16) float sW[32 * DIM];   // 8KB code tile
    __shared__ float  sB[32];
    __shared__ double sred[8];

    const int tid = threadIdx.x;
    const int i   = blockIdx.x * 256 + tid;
    const bool active = (i < nflag);
    const int token = active ? g_flags[i] : g_flags[0];

    float zr[DIM];
    float a = 0.0f;
    {
        const float4* zsrc = (const float4*)(z + (size_t)token * DIM);
        #pragma unroll
        for (int q = 0; q < 16; ++q) {
            float4 v = zsrc[q];
            zr[4 * q + 0] = v.x; zr[4 * q + 1] = v.y;
            zr[4 * q + 2] = v.z; zr[4 * q + 3] = v.w;
        }
        #pragma unroll
        for (int d = 0; d < DIM; ++d)
            a = __fadd_rn(a, __fmul_rn(zr[d], zr[d]));
    }

    float best = CUDART_INF_F;
    int   bidx = 0;

    for (int kt = 0; kt < KCODE / 32; ++kt) {
        __syncthreads();
        {
            const float4* wsrc = (const float4*)(w + (size_t)kt * 32 * DIM);
            float4* wdst = (float4*)sW;
            wdst[tid]       = wsrc[tid];
            wdst[tid + 256] = wsrc[tid + 256];
            if (tid < 32) sB[tid] = g_wsum2[kt * 32 + tid];
        }
        __syncthreads();

        #pragma unroll 1
        for (int k = 0; k < 32; k += 4) {
            const float* w0 = sW + (k + 0) * DIM;
            const float* w1 = sW + (k + 1) * DIM;
            const float* w2 = sW + (k + 2) * DIM;
            const float* w3 = sW + (k + 3) * DIM;
            float d0 = 0.0f, d1 = 0.0f, d2 = 0.0f, d3 = 0.0f;
            #pragma unroll
            for (int d = 0; d < DIM; ++d) {
                const float zv = zr[d];
                d0 = __fmaf_rn(zv, w0[d], d0);
                d1 = __fmaf_rn(zv, w1[d], d1);
                d2 = __fmaf_rn(zv, w2[d], d2);
                d3 = __fmaf_rn(zv, w3[d], d3);
            }
            const int kb = kt * 32 + k;
            float t, dd;
            t  = __fadd_rn(a, sB[k + 0]);
            dd = __fadd_rn(t, -__fmul_rn(2.0f, d0));
            if (dd < best) { best = dd; bidx = kb + 0; }
            t  = __fadd_rn(a, sB[k + 1]);
            dd = __fadd_rn(t, -__fmul_rn(2.0f, d1));
            if (dd < best) { best = dd; bidx = kb + 1; }
            t  = __fadd_rn(a, sB[k + 2]);
            dd = __fadd_rn(t, -__fmul_rn(2.0f, d2));
            if (dd < best) { best = dd; bidx = kb + 2; }
            t  = __fadd_rn(a, sB[k + 3]);
            dd = __fadd_rn(t, -__fmul_rn(2.0f, d3));
            if (dd < best) { best = dd; bidx = kb + 3; }
        }
    }

    double accd = 0.0;
    if (active) {
        g_idx[token]   = bidx;
        out_idx[token] = (float)bidx;
        const float4* wrow = (const float4*)(w + (size_t)bidx * DIM);
        float4* orow = (float4*)(out_zq + (size_t)token * DIM);
        #pragma unroll
        for (int j = 0; j < 16; ++j) {
            float4 wv = __ldg(wrow + j);
            const float zx = zr[4 * j + 0], zy = zr[4 * j + 1];
            const float zz = zr[4 * j + 2], zw = zr[4 * j + 3];
            const float dx = __fsub_rn(wv.x, zx);
            const float dy = __fsub_rn(wv.y, zy);
            const float dz = __fsub_rn(wv.z, zz);
            const float dw = __fsub_rn(wv.w, zw);
            float4 o;
            o.x = __fadd_rn(zx, dx);
            o.y = __fadd_rn(zy, dy);
            o.z = __fadd_rn(zz, dz);
            o.w = __fadd_rn(zw, dw);
            orow[j] = o;
            accd += (double)__fmul_rn(dx, dx);
            accd += (double)__fmul_rn(dy, dy);
            accd += (double)__fmul_rn(dz, dz);
            accd += (double)__fmul_rn(dw, dw);
        }
    }
    #pragma unroll
    for (int off = 16; off > 0; off >>= 1)
        accd += __shfl_down_sync(0xffffffffu, accd, off);
    if ((tid & 31) == 0) sred[tid >> 5] = accd;
    __syncthreads();
    if (tid == 0) {
        double v = 0.0;
        #pragma unroll
        for (int j = 0; j < 8; ++j) v += sred[j];
        g_part[1024 + blockIdx.x] = v;
    }
}

// ---------------------------------------------------------------------------
__global__ __launch_bounds__(256)
void k_final(float* __restrict__ out_loss, int total_elems)
{
    __shared__ double sm[8];
    const int tid = threadIdx.x;
    double s = 0.0;
    for (int i = tid; i < NPART; i += 256) s += g_part[i];
    #pragma unroll
    for (int off = 16; off > 0; off >>= 1)
        s += __shfl_down_sync(0xffffffffu, s, off);
    if ((tid & 31) == 0) sm[tid >> 5] = s;
    __syncthreads();
    if (tid == 0) {
        double tot = 0.0;
        #pragma unroll
        for (int i = 0; i < 8; ++i) tot += sm[i];
        const float m = (float)(tot / (double)total_elems);
        out_loss[0] = __fadd_rn(m, __fmul_rn(0.25f, m));
    }
}

// ---------------------------------------------------------------------------
extern "C" void kernel_launch(void* const* d_in, const int* in_sizes, int n_in,
                              void* d_out, int out_size)
{
    const float* z = (const float*)d_in[0];   // (N, 64) fp32
    const float* w = (const float*)d_in[1];   // (1024, 64) fp32

    const int ND = in_sizes[0];
    const int N  = ND / DIM;                  // 262144

    float* out      = (float*)d_out;
    float* out_zq   = out;                    // N*64 floats
    float* out_loss = out + (size_t)N * DIM;  // 1 float
    float* out_idx  = out_loss + 1;           // N floats

    k_prep_w<<<8, 256>>>(w);
    k_filter<<<N / 1024, 256>>>(z, w, out_zq, out_idx);
    k_exact2<<<N / 256, 256>>>(z, w, out_zq, out_idx);
    k_final<<<1, 256>>>(out_loss, ND);
}